// round 5
// baseline (speedup 1.0000x reference)
#include <cuda_runtime.h>

// ContextEmbedding: B=256, S=512, D=256. token ids in [0,76); special = [68,76);
// CLS=68, CONTEXT=69. Output f32 [B*S,256] = 134 MB -> store-path bound.
//
// R5: R2's proven shape (32 tok/warp, 512 blocks) + 256-bit stores (sm_100a
// st.global.v8.f32). Lane l owns the contiguous 32B chunk [8l,8l+8) of each
// row -> ONE store instruction per lane per row (was two STG.128). Zero rows
// (89.5%): 1 STG.256 per lane. Special rows: one LDG.256 gather (L1-resident
// 1KB table) + 1 STG.256. CLS/CONTEXT (~2.6%): tiny GEMV + warp-LN + ReLU.

#define D_MODEL        256
#define NUM_CONTEXT    16
#define SPECIAL_OFFSET 68
#define NUM_SPECIAL    8
#define LN_EPS         1e-5f
#define FULL           0xffffffffu
#define TOK_PER_WARP   32

__device__ __forceinline__ void stg256_cs(float* p, const float v[8]) {
    asm volatile(
        "st.global.cs.v8.f32 [%0], {%1,%2,%3,%4,%5,%6,%7,%8};"
        :: "l"(p),
           "f"(v[0]), "f"(v[1]), "f"(v[2]), "f"(v[3]),
           "f"(v[4]), "f"(v[5]), "f"(v[6]), "f"(v[7])
        : "memory");
}

__device__ __forceinline__ void ldg256(float v[8], const float* p) {
    asm volatile(
        "ld.global.nc.v8.f32 {%0,%1,%2,%3,%4,%5,%6,%7}, [%8];"
        : "=f"(v[0]), "=f"(v[1]), "=f"(v[2]), "=f"(v[3]),
          "=f"(v[4]), "=f"(v[5]), "=f"(v[6]), "=f"(v[7])
        : "l"(p));
}

__global__ __launch_bounds__(256) void context_embedding_kernel(
    const int*   __restrict__ token_ids,
    const float* __restrict__ context_features,  // [T,16]
    const float* __restrict__ special_table,     // [8,256]
    const float* __restrict__ cls_w,             // [3,256]
    const float* __restrict__ cls_b,
    const float* __restrict__ cls_ln_g,
    const float* __restrict__ cls_ln_b,
    const float* __restrict__ ctx_w,             // [16,256]
    const float* __restrict__ ctx_b,
    const float* __restrict__ ctx_ln_g,
    const float* __restrict__ ctx_ln_b,
    float*       __restrict__ out,               // [T,256]
    int T)
{
    const int warpId  = threadIdx.x >> 5;
    const int lane    = threadIdx.x & 31;
    const int tokBase = (blockIdx.x * 8 + warpId) * TOK_PER_WARP;
    if (tokBase >= T) return;

    // One coalesced 128B load of this warp's 32 token ids.
    const int myTok = token_ids[tokBase + lane];

    const bool isSpec = (myTok >= SPECIAL_OFFSET) && (myTok < SPECIAL_OFFSET + NUM_SPECIAL);
    const unsigned specMask = __ballot_sync(FULL, isSpec);
    const unsigned lnMask   = __ballot_sync(FULL, isSpec && (myTok <= SPECIAL_OFFSET + 1));

    const float z[8] = {0.f, 0.f, 0.f, 0.f, 0.f, 0.f, 0.f, 0.f};

    // Lane l owns the contiguous floats [8l, 8l+8) of each 256-float row.
    float* __restrict__ rowPtr = out + (size_t)tokBase * D_MODEL + lane * 8;

    #pragma unroll 4
    for (int t = 0; t < TOK_PER_WARP; t++, rowPtr += D_MODEL) {
        if (!((specMask >> t) & 1u)) {
            stg256_cs(rowPtr, z);          // zero row: single STG.256 per lane
            continue;
        }

        const int tok = __shfl_sync(FULL, myTok, t);
        const int sid = tok - SPECIAL_OFFSET;

        float e[8];
        ldg256(e, special_table + sid * D_MODEL + lane * 8);

        if ((lnMask >> t) & 1u) {
            // Rare branch (~2.6%): Linear -> LayerNorm -> ReLU, added on top.
            const bool is_cls = (sid == 0);
            const int K = is_cls ? 3 : NUM_CONTEXT;
            const float* __restrict__ w  = is_cls ? cls_w    : ctx_w;
            const float* __restrict__ bi = is_cls ? cls_b    : ctx_b;
            const float* __restrict__ g  = is_cls ? cls_ln_g : ctx_ln_g;
            const float* __restrict__ bb = is_cls ? cls_ln_b : ctx_ln_b;

            const float* __restrict__ f =
                context_features + (size_t)(tokBase + t) * NUM_CONTEXT;

            float h[8];
            ldg256(h, bi + lane * 8);

            for (int k = 0; k < K; k++) {
                const float fk = f[k];     // uniform address -> broadcast
                float wv[8];
                ldg256(wv, w + k * D_MODEL + lane * 8);
                #pragma unroll
                for (int j = 0; j < 8; j++) h[j] = fmaf(fk, wv[j], h[j]);
            }

            // LayerNorm over D=256: one-pass warp butterfly reduction.
            float s = 0.f, s2 = 0.f;
            #pragma unroll
            for (int j = 0; j < 8; j++) { s += h[j]; s2 += h[j] * h[j]; }
            #pragma unroll
            for (int off = 16; off > 0; off >>= 1) {
                s  += __shfl_xor_sync(FULL, s,  off);
                s2 += __shfl_xor_sync(FULL, s2, off);
            }
            const float mu   = s * (1.0f / D_MODEL);
            const float var  = fmaxf(s2 * (1.0f / D_MODEL) - mu * mu, 0.f);
            const float rstd = rsqrtf(var + LN_EPS);

            float gv[8], bv[8];
            ldg256(gv, g  + lane * 8);
            ldg256(bv, bb + lane * 8);
            #pragma unroll
            for (int j = 0; j < 8; j++)
                e[j] += fmaxf((h[j] - mu) * rstd * gv[j] + bv[j], 0.f);
        }

        stg256_cs(rowPtr, e);
    }
}

extern "C" void kernel_launch(void* const* d_in, const int* in_sizes, int n_in,
                              void* d_out, int out_size)
{
    const int*   token_ids        = (const int*)  d_in[0];
    const float* context_features = (const float*)d_in[1];
    const float* special_table    = (const float*)d_in[2];
    const float* cls_w            = (const float*)d_in[3];
    const float* cls_b            = (const float*)d_in[4];
    const float* cls_ln_g         = (const float*)d_in[5];
    const float* cls_ln_b         = (const float*)d_in[6];
    const float* ctx_w            = (const float*)d_in[7];
    const float* ctx_b            = (const float*)d_in[8];
    const float* ctx_ln_g         = (const float*)d_in[9];
    const float* ctx_ln_b         = (const float*)d_in[10];
    float* out = (float*)d_out;

    const int T = in_sizes[0];                         // B*S tokens = 131072
    const int tokens_per_block = 8 * TOK_PER_WARP;     // 256
    const int blocks = (T + tokens_per_block - 1) / tokens_per_block;  // 512

    context_embedding_kernel<<<blocks, 256>>>(
        token_ids, context_features, special_table,
        cls_w, cls_b, cls_ln_g, cls_ln_b,
        ctx_w, ctx_b, ctx_ln_g, ctx_ln_b,
        out, T);
}